// round 13
// baseline (speedup 1.0000x reference)
#include <cuda_runtime.h>
#include <math.h>

// ---------------------------------------------------------------------------
// SelfAttention (feature attention), fp32 exact path.
//
// Per branch (inp [N=8192, M=2048], all W [2048,2048]):
//   K = inp@Kw + Kb ; Q = inp@Qw + Qb ; V = inp@Vw + Vb     (N x D)
//   att = Q^T @ K                                            (D x D)
//   w   = softmax_rows(att)        -> written directly to output
//   T   = V @ w^T                                            (N x D)
//   Y   = T @ Ow + Ob + inp        -> written directly to output
//
// Everything fp32 FFMA: softmax logits have magnitude ~30, and w is a checked
// output, so logit abs-error must be <<1e-3 -> needs fp32-class precision.
// ---------------------------------------------------------------------------

#define BM 128
#define BN 128
#define BK 16

static const int NN = 8192;
static const int DD = 2048;

// Scratch (allocation-free rule: __device__ globals)
__device__ float g_K[8192u * 2048u];
__device__ float g_Q[8192u * 2048u];
__device__ float g_V[8192u * 2048u];
__device__ float g_T[8192u * 2048u];
__device__ float g_att[2048u * 2048u];

// AMODE: 0 -> A(n,k) = A[n*lda + k]   (row-major [N,K])
//        1 -> A(n,k) = A[k*lda + n]   (transposed access, for Q^T)
// BMODE: 0 -> B(k,m) = B[k*ldb + m]   (row-major [K,M])
//        1 -> B(k,m) = B[m*ldb + k]   (transposed access, for w^T)
template <int AMODE, int BMODE, bool HAS_BIAS, bool ADD_RES>
__global__ __launch_bounds__(256, 2)
void sgemm_kernel(const float* __restrict__ A, int lda,
                  const float* __restrict__ B, int ldb,
                  const float* __restrict__ bias,
                  const float* __restrict__ res,
                  float* __restrict__ C,
                  int M, int Kdim)
{
    __shared__ float As[BK][BM];
    __shared__ float Bs[BK][BN];

    const int tid  = threadIdx.x;
    const int row0 = blockIdx.y * BM;
    const int col0 = blockIdx.x * BN;
    const int ty   = tid >> 4;   // 0..15
    const int tx   = tid & 15;   // 0..15

    float acc[8][8];
#pragma unroll
    for (int i = 0; i < 8; i++)
#pragma unroll
        for (int j = 0; j < 8; j++) acc[i][j] = 0.0f;

    for (int k0 = 0; k0 < Kdim; k0 += BK) {
        // ---- load A tile into As[k][n_local] ----
        if (AMODE == 0) {
#pragma unroll
            for (int p = 0; p < 2; p++) {
                int ar = (tid >> 2) + p * 64;        // row within tile
                int ac = (tid & 3) * 4;              // k within tile
                float4 v = *(const float4*)(A + (size_t)(row0 + ar) * lda + k0 + ac);
                As[ac + 0][ar] = v.x;
                As[ac + 1][ar] = v.y;
                As[ac + 2][ar] = v.z;
                As[ac + 3][ar] = v.w;
            }
        } else {
#pragma unroll
            for (int p = 0; p < 2; p++) {
                int ak = (tid >> 5) + p * 8;         // k within tile
                int ai = (tid & 31) * 4;             // row within tile (contiguous)
                *(float4*)&As[ak][ai] =
                    *(const float4*)(A + (size_t)(k0 + ak) * lda + row0 + ai);
            }
        }
        // ---- load B tile into Bs[k][m_local] ----
        if (BMODE == 0) {
#pragma unroll
            for (int p = 0; p < 2; p++) {
                int bk = (tid >> 5) + p * 8;
                int bm = (tid & 31) * 4;
                *(float4*)&Bs[bk][bm] =
                    *(const float4*)(B + (size_t)(k0 + bk) * ldb + col0 + bm);
            }
        } else {
#pragma unroll
            for (int p = 0; p < 2; p++) {
                int bm = (tid >> 2) + p * 64;        // m within tile
                int bk = (tid & 3) * 4;              // k within tile (contiguous)
                float4 v = *(const float4*)(B + (size_t)(col0 + bm) * ldb + k0 + bk);
                Bs[bk + 0][bm] = v.x;
                Bs[bk + 1][bm] = v.y;
                Bs[bk + 2][bm] = v.z;
                Bs[bk + 3][bm] = v.w;
            }
        }
        __syncthreads();

#pragma unroll
        for (int kk = 0; kk < BK; kk++) {
            float a[8], b[8];
            *(float4*)&a[0] = *(const float4*)&As[kk][ty * 8];
            *(float4*)&a[4] = *(const float4*)&As[kk][ty * 8 + 4];
            *(float4*)&b[0] = *(const float4*)&Bs[kk][tx * 8];
            *(float4*)&b[4] = *(const float4*)&Bs[kk][tx * 8 + 4];
#pragma unroll
            for (int i = 0; i < 8; i++)
#pragma unroll
                for (int j = 0; j < 8; j++)
                    acc[i][j] = fmaf(a[i], b[j], acc[i][j]);
        }
        __syncthreads();
    }

    // ---- epilogue: bias + residual + store ----
#pragma unroll
    for (int i = 0; i < 8; i++) {
        const int r = row0 + ty * 8 + i;
#pragma unroll
        for (int j = 0; j < 8; j += 4) {
            const int c = col0 + tx * 8 + j;
            float4 o;
            o.x = acc[i][j + 0];
            o.y = acc[i][j + 1];
            o.z = acc[i][j + 2];
            o.w = acc[i][j + 3];
            if (HAS_BIAS) {
                float4 bv = *(const float4*)(bias + c);
                o.x += bv.x; o.y += bv.y; o.z += bv.z; o.w += bv.w;
            }
            if (ADD_RES) {
                float4 rv = *(const float4*)(res + (size_t)r * M + c);
                o.x += rv.x; o.y += rv.y; o.z += rv.z; o.w += rv.w;
            }
            *(float4*)(C + (size_t)r * M + c) = o;
        }
    }
}

// Row softmax: one block per row (D = 2048), 256 threads.
__global__ __launch_bounds__(256)
void softmax_rows_kernel(const float* __restrict__ A, float* __restrict__ W, int D)
{
    const int row = blockIdx.x;
    const float* a = A + (size_t)row * D;
    float* w = W + (size_t)row * D;
    __shared__ float red[256];
    const int tid = threadIdx.x;

    float m = -INFINITY;
    for (int j = tid; j < D; j += 256) m = fmaxf(m, a[j]);
    red[tid] = m;
    __syncthreads();
    for (int s = 128; s > 0; s >>= 1) {
        if (tid < s) red[tid] = fmaxf(red[tid], red[tid + s]);
        __syncthreads();
    }
    m = red[0];
    __syncthreads();

    float sum = 0.0f;
    for (int j = tid; j < D; j += 256) {
        float e = expf(a[j] - m);
        w[j] = e;
        sum += e;
    }
    red[tid] = sum;
    __syncthreads();
    for (int s = 128; s > 0; s >>= 1) {
        if (tid < s) red[tid] += red[tid + s];
        __syncthreads();
    }
    const float inv = 1.0f / red[0];
    for (int j = tid; j < D; j += 256) w[j] *= inv;
}

static void run_branch(const float* inp,
                       const float* Kw, const float* Kb,
                       const float* Qw, const float* Qb,
                       const float* Vw, const float* Vb,
                       const float* Ow, const float* Ob,
                       float* outY, float* outW,
                       float* bK, float* bQ, float* bV, float* bAtt, float* bT)
{
    dim3 blk(256);
    dim3 gP(DD / BN, NN / BM);   // 16 x 64 : [8192 x 2048] outputs
    dim3 gA(DD / BN, DD / BM);   // 16 x 16 : [2048 x 2048] output

    // K, Q, V projections (NN, +bias)
    sgemm_kernel<0, 0, true, false><<<gP, blk>>>(inp, DD, Kw, DD, Kb, nullptr, bK, DD, DD);
    sgemm_kernel<0, 0, true, false><<<gP, blk>>>(inp, DD, Qw, DD, Qb, nullptr, bQ, DD, DD);
    sgemm_kernel<0, 0, true, false><<<gP, blk>>>(inp, DD, Vw, DD, Vb, nullptr, bV, DD, DD);

    // att = Q^T @ K  (TN over n=8192)
    sgemm_kernel<1, 0, false, false><<<gA, blk>>>(bQ, DD, bK, DD, nullptr, nullptr, bAtt, DD, NN);

    // w = softmax(att) rows -> directly into output
    softmax_rows_kernel<<<DD, blk>>>(bAtt, outW, DD);

    // T = V @ w^T  (NT)
    sgemm_kernel<0, 1, false, false><<<gP, blk>>>(bV, DD, outW, DD, nullptr, nullptr, bT, DD, DD);

    // Y = T @ Ow + Ob + inp  (NN, +bias, +residual) -> directly into output
    sgemm_kernel<0, 0, true, true><<<gP, blk>>>(bT, DD, Ow, DD, Ob, inp, outY, DD, DD);
}

extern "C" void kernel_launch(void* const* d_in, const int* in_sizes, int n_in,
                              void* d_out, int out_size)
{
    const float* x    = (const float*)d_in[0];
    const float* y    = (const float*)d_in[1];
    const float* QK_w = (const float*)d_in[2];
    const float* QK_b = (const float*)d_in[3];
    const float* QQ_w = (const float*)d_in[4];
    const float* QQ_b = (const float*)d_in[5];
    const float* QV_w = (const float*)d_in[6];
    const float* QV_b = (const float*)d_in[7];
    const float* QO_w = (const float*)d_in[8];
    const float* QO_b = (const float*)d_in[9];
    const float* FK_w = (const float*)d_in[10];
    const float* FK_b = (const float*)d_in[11];
    const float* FQ_w = (const float*)d_in[12];
    const float* FQ_b = (const float*)d_in[13];
    const float* FV_w = (const float*)d_in[14];
    const float* FV_b = (const float*)d_in[15];
    const float* FO_w = (const float*)d_in[16];
    const float* FO_b = (const float*)d_in[17];

    float* out = (float*)d_out;
    const size_t SZ_Y = (size_t)NN * DD;   // 16,777,216
    const size_t SZ_W = (size_t)DD * DD;   //  4,194,304
    float* outQy   = out;
    float* outQatt = out + SZ_Y;
    float* outFy   = out + SZ_Y + SZ_W;
    float* outFatt = out + 2 * SZ_Y + SZ_W;

    float *pK, *pQ, *pV, *pAtt, *pT;
    cudaGetSymbolAddress((void**)&pK,   g_K);
    cudaGetSymbolAddress((void**)&pQ,   g_Q);
    cudaGetSymbolAddress((void**)&pV,   g_V);
    cudaGetSymbolAddress((void**)&pAtt, g_att);
    cudaGetSymbolAddress((void**)&pT,   g_T);

    run_branch(x, QK_w, QK_b, QQ_w, QQ_b, QV_w, QV_b, QO_w, QO_b,
               outQy, outQatt, pK, pQ, pV, pAtt, pT);
    run_branch(y, FK_w, FK_b, FQ_w, FQ_b, FV_w, FV_b, FO_w, FO_b,
               outFy, outFatt, pK, pQ, pV, pAtt, pT);
}

// round 14
// speedup vs baseline: 1.0010x; 1.0010x over previous
#include <cuda_runtime.h>
#include <math.h>

// ---------------------------------------------------------------------------
// SelfAttention (feature attention), fp32 exact path.
//
// Per branch (inp [N=8192, M=2048], all W [2048,2048]):
//   K = inp@Kw + Kb ; Q = inp@Qw + Qb ; V = inp@Vw + Vb     (N x D)
//   att = Q^T @ K                                            (D x D)
//   w   = softmax_rows(att)        -> written directly to output
//   T   = V @ w^T                                            (N x D)
//   Y   = T @ Ow + Ob + inp        -> written directly to output
//
// Everything fp32 FFMA: softmax logits have magnitude ~30, and w is a checked
// output, so logit abs-error must be <<1e-3 -> needs fp32-class precision.
// ---------------------------------------------------------------------------

#define BM 128
#define BN 128
#define BK 16

static const int NN = 8192;
static const int DD = 2048;

// Scratch (allocation-free rule: __device__ globals)
__device__ float g_K[8192u * 2048u];
__device__ float g_Q[8192u * 2048u];
__device__ float g_V[8192u * 2048u];
__device__ float g_T[8192u * 2048u];
__device__ float g_att[2048u * 2048u];

// AMODE: 0 -> A(n,k) = A[n*lda + k]   (row-major [N,K])
//        1 -> A(n,k) = A[k*lda + n]   (transposed access, for Q^T)
// BMODE: 0 -> B(k,m) = B[k*ldb + m]   (row-major [K,M])
//        1 -> B(k,m) = B[m*ldb + k]   (transposed access, for w^T)
template <int AMODE, int BMODE, bool HAS_BIAS, bool ADD_RES>
__global__ __launch_bounds__(256, 2)
void sgemm_kernel(const float* __restrict__ A, int lda,
                  const float* __restrict__ B, int ldb,
                  const float* __restrict__ bias,
                  const float* __restrict__ res,
                  float* __restrict__ C,
                  int M, int Kdim)
{
    __shared__ float As[BK][BM];
    __shared__ float Bs[BK][BN];

    const int tid  = threadIdx.x;
    const int row0 = blockIdx.y * BM;
    const int col0 = blockIdx.x * BN;
    const int ty   = tid >> 4;   // 0..15
    const int tx   = tid & 15;   // 0..15

    float acc[8][8];
#pragma unroll
    for (int i = 0; i < 8; i++)
#pragma unroll
        for (int j = 0; j < 8; j++) acc[i][j] = 0.0f;

    for (int k0 = 0; k0 < Kdim; k0 += BK) {
        // ---- load A tile into As[k][n_local] ----
        if (AMODE == 0) {
#pragma unroll
            for (int p = 0; p < 2; p++) {
                int ar = (tid >> 2) + p * 64;        // row within tile
                int ac = (tid & 3) * 4;              // k within tile
                float4 v = *(const float4*)(A + (size_t)(row0 + ar) * lda + k0 + ac);
                As[ac + 0][ar] = v.x;
                As[ac + 1][ar] = v.y;
                As[ac + 2][ar] = v.z;
                As[ac + 3][ar] = v.w;
            }
        } else {
#pragma unroll
            for (int p = 0; p < 2; p++) {
                int ak = (tid >> 5) + p * 8;         // k within tile
                int ai = (tid & 31) * 4;             // row within tile (contiguous)
                *(float4*)&As[ak][ai] =
                    *(const float4*)(A + (size_t)(k0 + ak) * lda + row0 + ai);
            }
        }
        // ---- load B tile into Bs[k][m_local] ----
        if (BMODE == 0) {
#pragma unroll
            for (int p = 0; p < 2; p++) {
                int bk = (tid >> 5) + p * 8;
                int bm = (tid & 31) * 4;
                *(float4*)&Bs[bk][bm] =
                    *(const float4*)(B + (size_t)(k0 + bk) * ldb + col0 + bm);
            }
        } else {
#pragma unroll
            for (int p = 0; p < 2; p++) {
                int bm = (tid >> 2) + p * 64;        // m within tile
                int bk = (tid & 3) * 4;              // k within tile (contiguous)
                float4 v = *(const float4*)(B + (size_t)(col0 + bm) * ldb + k0 + bk);
                Bs[bk + 0][bm] = v.x;
                Bs[bk + 1][bm] = v.y;
                Bs[bk + 2][bm] = v.z;
                Bs[bk + 3][bm] = v.w;
            }
        }
        __syncthreads();

#pragma unroll
        for (int kk = 0; kk < BK; kk++) {
            float a[8], b[8];
            *(float4*)&a[0] = *(const float4*)&As[kk][ty * 8];
            *(float4*)&a[4] = *(const float4*)&As[kk][ty * 8 + 4];
            *(float4*)&b[0] = *(const float4*)&Bs[kk][tx * 8];
            *(float4*)&b[4] = *(const float4*)&Bs[kk][tx * 8 + 4];
#pragma unroll
            for (int i = 0; i < 8; i++)
#pragma unroll
                for (int j = 0; j < 8; j++)
                    acc[i][j] = fmaf(a[i], b[j], acc[i][j]);
        }
        __syncthreads();
    }

    // ---- epilogue: bias + residual + store ----
#pragma unroll
    for (int i = 0; i < 8; i++) {
        const int r = row0 + ty * 8 + i;
#pragma unroll
        for (int j = 0; j < 8; j += 4) {
            const int c = col0 + tx * 8 + j;
            float4 o;
            o.x = acc[i][j + 0];
            o.y = acc[i][j + 1];
            o.z = acc[i][j + 2];
            o.w = acc[i][j + 3];
            if (HAS_BIAS) {
                float4 bv = *(const float4*)(bias + c);
                o.x += bv.x; o.y += bv.y; o.z += bv.z; o.w += bv.w;
            }
            if (ADD_RES) {
                float4 rv = *(const float4*)(res + (size_t)r * M + c);
                o.x += rv.x; o.y += rv.y; o.z += rv.z; o.w += rv.w;
            }
            *(float4*)(C + (size_t)r * M + c) = o;
        }
    }
}

// Row softmax: one block per row (D = 2048), 256 threads.
__global__ __launch_bounds__(256)
void softmax_rows_kernel(const float* __restrict__ A, float* __restrict__ W, int D)
{
    const int row = blockIdx.x;
    const float* a = A + (size_t)row * D;
    float* w = W + (size_t)row * D;
    __shared__ float red[256];
    const int tid = threadIdx.x;

    float m = -INFINITY;
    for (int j = tid; j < D; j += 256) m = fmaxf(m, a[j]);
    red[tid] = m;
    __syncthreads();
    for (int s = 128; s > 0; s >>= 1) {
        if (tid < s) red[tid] = fmaxf(red[tid], red[tid + s]);
        __syncthreads();
    }
    m = red[0];
    __syncthreads();

    float sum = 0.0f;
    for (int j = tid; j < D; j += 256) {
        float e = expf(a[j] - m);
        w[j] = e;
        sum += e;
    }
    red[tid] = sum;
    __syncthreads();
    for (int s = 128; s > 0; s >>= 1) {
        if (tid < s) red[tid] += red[tid + s];
        __syncthreads();
    }
    const float inv = 1.0f / red[0];
    for (int j = tid; j < D; j += 256) w[j] *= inv;
}

static void run_branch(const float* inp,
                       const float* Kw, const float* Kb,
                       const float* Qw, const float* Qb,
                       const float* Vw, const float* Vb,
                       const float* Ow, const float* Ob,
                       float* outY, float* outW,
                       float* bK, float* bQ, float* bV, float* bAtt, float* bT)
{
    dim3 blk(256);
    dim3 gP(DD / BN, NN / BM);   // 16 x 64 : [8192 x 2048] outputs
    dim3 gA(DD / BN, DD / BM);   // 16 x 16 : [2048 x 2048] output

    // K, Q, V projections (NN, +bias)
    sgemm_kernel<0, 0, true, false><<<gP, blk>>>(inp, DD, Kw, DD, Kb, nullptr, bK, DD, DD);
    sgemm_kernel<0, 0, true, false><<<gP, blk>>>(inp, DD, Qw, DD, Qb, nullptr, bQ, DD, DD);
    sgemm_kernel<0, 0, true, false><<<gP, blk>>>(inp, DD, Vw, DD, Vb, nullptr, bV, DD, DD);

    // att = Q^T @ K  (TN over n=8192)
    sgemm_kernel<1, 0, false, false><<<gA, blk>>>(bQ, DD, bK, DD, nullptr, nullptr, bAtt, DD, NN);

    // w = softmax(att) rows -> directly into output
    softmax_rows_kernel<<<DD, blk>>>(bAtt, outW, DD);

    // T = V @ w^T  (NT)
    sgemm_kernel<0, 1, false, false><<<gP, blk>>>(bV, DD, outW, DD, nullptr, nullptr, bT, DD, DD);

    // Y = T @ Ow + Ob + inp  (NN, +bias, +residual) -> directly into output
    sgemm_kernel<0, 0, true, true><<<gP, blk>>>(bT, DD, Ow, DD, Ob, inp, outY, DD, DD);
}

extern "C" void kernel_launch(void* const* d_in, const int* in_sizes, int n_in,
                              void* d_out, int out_size)
{
    const float* x    = (const float*)d_in[0];
    const float* y    = (const float*)d_in[1];
    const float* QK_w = (const float*)d_in[2];
    const float* QK_b = (const float*)d_in[3];
    const float* QQ_w = (const float*)d_in[4];
    const float* QQ_b = (const float*)d_in[5];
    const float* QV_w = (const float*)d_in[6];
    const float* QV_b = (const float*)d_in[7];
    const float* QO_w = (const float*)d_in[8];
    const float* QO_b = (const float*)d_in[9];
    const float* FK_w = (const float*)d_in[10];
    const float* FK_b = (const float*)d_in[11];
    const float* FQ_w = (const float*)d_in[12];
    const float* FQ_b = (const float*)d_in[13];
    const float* FV_w = (const float*)d_in[14];
    const float* FV_b = (const float*)d_in[15];
    const float* FO_w = (const float*)d_in[16];
    const float* FO_b = (const float*)d_in[17];

    float* out = (float*)d_out;
    const size_t SZ_Y = (size_t)NN * DD;   // 16,777,216
    const size_t SZ_W = (size_t)DD * DD;   //  4,194,304
    float* outQy   = out;
    float* outQatt = out + SZ_Y;
    float* outFy   = out + SZ_Y + SZ_W;
    float* outFatt = out + 2 * SZ_Y + SZ_W;

    float *pK, *pQ, *pV, *pAtt, *pT;
    cudaGetSymbolAddress((void**)&pK,   g_K);
    cudaGetSymbolAddress((void**)&pQ,   g_Q);
    cudaGetSymbolAddress((void**)&pV,   g_V);
    cudaGetSymbolAddress((void**)&pAtt, g_att);
    cudaGetSymbolAddress((void**)&pT,   g_T);

    run_branch(x, QK_w, QK_b, QQ_w, QQ_b, QV_w, QV_b, QO_w, QO_b,
               outQy, outQatt, pK, pQ, pV, pAtt, pT);
    run_branch(y, FK_w, FK_b, FQ_w, FQ_b, FV_w, FV_b, FO_w, FO_b,
               outFy, outFatt, pK, pQ, pV, pAtt, pT);
}